// round 5
// baseline (speedup 1.0000x reference)
#include <cuda_runtime.h>
#include <cuda_bf16.h>

// Problem: B=16, C=64, H=128, W=128.
// loss = sum_{b,c} [ sum_hw |pre-gt|*mask / max(count_nonzero(mask),1) ] / B
//
// Single fused kernel: one CTA per (b,c) plane (1024 CTAs, 256 threads).
//   - float4 loads of pre/gt/mask, unrolled x4 (12 LDG.128 in flight/thread)
//   - block reduction -> plane value in __device__ scratch
//   - last-arriving CTA sums all 1024 plane values in fixed order
//     (deterministic) and writes out[0], then resets the arrival counter
//     so graph replays are clean.

#define NPLANES 1024
#define PLANE_ELEMS 16384           // 128*128
#define PLANE_VEC4 (PLANE_ELEMS/4)  // 4096
#define THREADS 256
#define BATCH 16.0f

__device__ float g_plane_loss[NPLANES];
__device__ unsigned int g_arrived;   // zero-initialized at load; reset by last CTA

__global__ __launch_bounds__(THREADS) void fused_l1_kernel(
    const float* __restrict__ pre,
    const float* __restrict__ gt,
    const float* __restrict__ mask,
    float* __restrict__ out)
{
    const int plane = blockIdx.x;
    const size_t base = (size_t)plane * PLANE_ELEMS;
    const float4* __restrict__ p4 = (const float4*)(pre  + base);
    const float4* __restrict__ g4 = (const float4*)(gt   + base);
    const float4* __restrict__ m4 = (const float4*)(mask + base);

    float s = 0.0f;   // masked L1 sum
    float c = 0.0f;   // nonzero count

    // 4096 vec4 / 256 threads = 16 iters; unroll x4 -> 4 outer iters,
    // 12 independent LDG.128 front-batched per iter for deep MLP.
    for (int i = threadIdx.x; i < PLANE_VEC4; i += 4 * THREADS) {
        float4 a0 = p4[i];
        float4 b0 = g4[i];
        float4 m0 = m4[i];
        float4 a1 = p4[i + THREADS];
        float4 b1 = g4[i + THREADS];
        float4 m1 = m4[i + THREADS];
        float4 a2 = p4[i + 2 * THREADS];
        float4 b2 = g4[i + 2 * THREADS];
        float4 m2 = m4[i + 2 * THREADS];
        float4 a3 = p4[i + 3 * THREADS];
        float4 b3 = g4[i + 3 * THREADS];
        float4 m3 = m4[i + 3 * THREADS];

        s += fabsf(a0.x - b0.x) * m0.x;
        s += fabsf(a0.y - b0.y) * m0.y;
        s += fabsf(a0.z - b0.z) * m0.z;
        s += fabsf(a0.w - b0.w) * m0.w;
        c += (m0.x != 0.0f) ? 1.0f : 0.0f;
        c += (m0.y != 0.0f) ? 1.0f : 0.0f;
        c += (m0.z != 0.0f) ? 1.0f : 0.0f;
        c += (m0.w != 0.0f) ? 1.0f : 0.0f;

        s += fabsf(a1.x - b1.x) * m1.x;
        s += fabsf(a1.y - b1.y) * m1.y;
        s += fabsf(a1.z - b1.z) * m1.z;
        s += fabsf(a1.w - b1.w) * m1.w;
        c += (m1.x != 0.0f) ? 1.0f : 0.0f;
        c += (m1.y != 0.0f) ? 1.0f : 0.0f;
        c += (m1.z != 0.0f) ? 1.0f : 0.0f;
        c += (m1.w != 0.0f) ? 1.0f : 0.0f;

        s += fabsf(a2.x - b2.x) * m2.x;
        s += fabsf(a2.y - b2.y) * m2.y;
        s += fabsf(a2.z - b2.z) * m2.z;
        s += fabsf(a2.w - b2.w) * m2.w;
        c += (m2.x != 0.0f) ? 1.0f : 0.0f;
        c += (m2.y != 0.0f) ? 1.0f : 0.0f;
        c += (m2.z != 0.0f) ? 1.0f : 0.0f;
        c += (m2.w != 0.0f) ? 1.0f : 0.0f;

        s += fabsf(a3.x - b3.x) * m3.x;
        s += fabsf(a3.y - b3.y) * m3.y;
        s += fabsf(a3.z - b3.z) * m3.z;
        s += fabsf(a3.w - b3.w) * m3.w;
        c += (m3.x != 0.0f) ? 1.0f : 0.0f;
        c += (m3.y != 0.0f) ? 1.0f : 0.0f;
        c += (m3.z != 0.0f) ? 1.0f : 0.0f;
        c += (m3.w != 0.0f) ? 1.0f : 0.0f;
    }

    // warp reduce
    #pragma unroll
    for (int off = 16; off > 0; off >>= 1) {
        s += __shfl_xor_sync(0xFFFFFFFFu, s, off);
        c += __shfl_xor_sync(0xFFFFFFFFu, c, off);
    }

    __shared__ float ss[THREADS / 32];
    __shared__ float sc[THREADS / 32];
    __shared__ int s_is_last;
    const int wid = threadIdx.x >> 5;
    const int lid = threadIdx.x & 31;
    if (lid == 0) { ss[wid] = s; sc[wid] = c; }
    __syncthreads();

    if (wid == 0) {
        s = (lid < THREADS / 32) ? ss[lid] : 0.0f;
        c = (lid < THREADS / 32) ? sc[lid] : 0.0f;
        #pragma unroll
        for (int off = 4; off > 0; off >>= 1) {
            s += __shfl_xor_sync(0xFFFFFFFFu, s, off);
            c += __shfl_xor_sync(0xFFFFFFFFu, c, off);
        }
        if (lid == 0)
            g_plane_loss[plane] = s / fmaxf(c, 1.0f);
    }

    // ---- last-CTA finalize ----
    __threadfence();  // make g_plane_loss[plane] visible before counting arrival
    if (threadIdx.x == 0) {
        unsigned int prev = atomicAdd(&g_arrived, 1u);
        s_is_last = (prev == NPLANES - 1) ? 1 : 0;
    }
    __syncthreads();

    if (s_is_last) {
        // Fixed-order, single-block reduction of 1024 plane values
        // (deterministic across replays).
        float t = 0.0f;
        #pragma unroll
        for (int i = threadIdx.x; i < NPLANES; i += THREADS)
            t += g_plane_loss[i];

        #pragma unroll
        for (int off = 16; off > 0; off >>= 1)
            t += __shfl_xor_sync(0xFFFFFFFFu, t, off);

        if (lid == 0) ss[wid] = t;
        __syncthreads();

        if (wid == 0) {
            t = (lid < THREADS / 32) ? ss[lid] : 0.0f;
            #pragma unroll
            for (int off = 4; off > 0; off >>= 1)
                t += __shfl_xor_sync(0xFFFFFFFFu, t, off);
            if (lid == 0) {
                out[0] = t / BATCH;
                g_arrived = 0;   // reset for next graph replay
            }
        }
    }
}

extern "C" void kernel_launch(void* const* d_in, const int* in_sizes, int n_in,
                              void* d_out, int out_size)
{
    const float* pre  = (const float*)d_in[0];
    const float* gt   = (const float*)d_in[1];
    const float* mask = (const float*)d_in[2];
    float* out = (float*)d_out;

    fused_l1_kernel<<<NPLANES, THREADS>>>(pre, gt, mask, out);
}

// round 7
// speedup vs baseline: 1.1030x; 1.1030x over previous
#include <cuda_runtime.h>
#include <cuda_bf16.h>

// Problem: B=16, C=64, H=128, W=128.
// loss = sum_{b,c} [ sum_hw |pre-gt|*mask / max(count_nonzero(mask),1) ] / B
//
// Single fused kernel: one CTA per (b,c) plane (1024 CTAs, 256 threads).
//   - float4 loads of pre/gt/mask, unrolled x2 (6 LDG.128 in flight/thread;
//     x4 measured SLOWER: L1tex wavefront-queue contention at occ 8,
//     DRAM 65% vs 75%)
//   - block reduction -> plane value in __device__ scratch
//   - last-arriving CTA sums all 1024 plane values in fixed order
//     (deterministic) and writes out[0], then resets the arrival counter
//     so graph replays are clean.

#define NPLANES 1024
#define PLANE_ELEMS 16384           // 128*128
#define PLANE_VEC4 (PLANE_ELEMS/4)  // 4096
#define THREADS 256
#define BATCH 16.0f

__device__ float g_plane_loss[NPLANES];
__device__ unsigned int g_arrived;   // zero-initialized at load; reset by last CTA

__global__ __launch_bounds__(THREADS) void fused_l1_kernel(
    const float* __restrict__ pre,
    const float* __restrict__ gt,
    const float* __restrict__ mask,
    float* __restrict__ out)
{
    const int plane = blockIdx.x;
    const size_t base = (size_t)plane * PLANE_ELEMS;
    const float4* __restrict__ p4 = (const float4*)(pre  + base);
    const float4* __restrict__ g4 = (const float4*)(gt   + base);
    const float4* __restrict__ m4 = (const float4*)(mask + base);

    float s = 0.0f;   // masked L1 sum
    float c = 0.0f;   // nonzero count

    // 4096 vec4 / 256 threads = 16 iters; unroll x2 -> 8 outer iters,
    // 6 independent LDG.128 front-batched per iter (sweet spot at occ 8).
    for (int i = threadIdx.x; i < PLANE_VEC4; i += 2 * THREADS) {
        float4 a0 = p4[i];
        float4 b0 = g4[i];
        float4 m0 = m4[i];
        float4 a1 = p4[i + THREADS];
        float4 b1 = g4[i + THREADS];
        float4 m1 = m4[i + THREADS];

        s += fabsf(a0.x - b0.x) * m0.x;
        s += fabsf(a0.y - b0.y) * m0.y;
        s += fabsf(a0.z - b0.z) * m0.z;
        s += fabsf(a0.w - b0.w) * m0.w;
        c += (m0.x != 0.0f) ? 1.0f : 0.0f;
        c += (m0.y != 0.0f) ? 1.0f : 0.0f;
        c += (m0.z != 0.0f) ? 1.0f : 0.0f;
        c += (m0.w != 0.0f) ? 1.0f : 0.0f;

        s += fabsf(a1.x - b1.x) * m1.x;
        s += fabsf(a1.y - b1.y) * m1.y;
        s += fabsf(a1.z - b1.z) * m1.z;
        s += fabsf(a1.w - b1.w) * m1.w;
        c += (m1.x != 0.0f) ? 1.0f : 0.0f;
        c += (m1.y != 0.0f) ? 1.0f : 0.0f;
        c += (m1.z != 0.0f) ? 1.0f : 0.0f;
        c += (m1.w != 0.0f) ? 1.0f : 0.0f;
    }

    // warp reduce
    #pragma unroll
    for (int off = 16; off > 0; off >>= 1) {
        s += __shfl_xor_sync(0xFFFFFFFFu, s, off);
        c += __shfl_xor_sync(0xFFFFFFFFu, c, off);
    }

    __shared__ float ss[THREADS / 32];
    __shared__ float sc[THREADS / 32];
    __shared__ int s_is_last;
    const int wid = threadIdx.x >> 5;
    const int lid = threadIdx.x & 31;
    if (lid == 0) { ss[wid] = s; sc[wid] = c; }
    __syncthreads();

    if (wid == 0) {
        s = (lid < THREADS / 32) ? ss[lid] : 0.0f;
        c = (lid < THREADS / 32) ? sc[lid] : 0.0f;
        #pragma unroll
        for (int off = 4; off > 0; off >>= 1) {
            s += __shfl_xor_sync(0xFFFFFFFFu, s, off);
            c += __shfl_xor_sync(0xFFFFFFFFu, c, off);
        }
        if (lid == 0)
            g_plane_loss[plane] = s / fmaxf(c, 1.0f);
    }

    // ---- last-CTA finalize ----
    __threadfence();  // make g_plane_loss[plane] visible before counting arrival
    if (threadIdx.x == 0) {
        unsigned int prev = atomicAdd(&g_arrived, 1u);
        s_is_last = (prev == NPLANES - 1) ? 1 : 0;
    }
    __syncthreads();

    if (s_is_last) {
        // Fixed-order, single-block reduction of 1024 plane values
        // (deterministic across replays).
        float t = 0.0f;
        #pragma unroll
        for (int i = threadIdx.x; i < NPLANES; i += THREADS)
            t += g_plane_loss[i];

        #pragma unroll
        for (int off = 16; off > 0; off >>= 1)
            t += __shfl_xor_sync(0xFFFFFFFFu, t, off);

        if (lid == 0) ss[wid] = t;
        __syncthreads();

        if (wid == 0) {
            t = (lid < THREADS / 32) ? ss[lid] : 0.0f;
            #pragma unroll
            for (int off = 4; off > 0; off >>= 1)
                t += __shfl_xor_sync(0xFFFFFFFFu, t, off);
            if (lid == 0) {
                out[0] = t / BATCH;
                g_arrived = 0;   // reset for next graph replay
            }
        }
    }
}

extern "C" void kernel_launch(void* const* d_in, const int* in_sizes, int n_in,
                              void* d_out, int out_size)
{
    const float* pre  = (const float*)d_in[0];
    const float* gt   = (const float*)d_in[1];
    const float* mask = (const float*)d_in[2];
    float* out = (float*)d_out;

    fused_l1_kernel<<<NPLANES, THREADS>>>(pre, gt, mask, out);
}